// round 13
// baseline (speedup 1.0000x reference)
#include <cuda_runtime.h>
#include <math.h>

#define MAXN 50048
#define MAXE 1650080

// ------------ static device scratch (zero-initialized at load) -----------
__device__ float d_h1[MAXN * 64];
__device__ float d_as1[MAXN * 8];
__device__ float d_ad1[MAXN * 8];
__device__ float d_x1[MAXN * 64];
__device__ float d_z[MAXN * 64];
__device__ float d_as2[MAXN];
__device__ float d_ad2[MAXN];
__device__ float d_wsrc[64];
__device__ float d_wdst[64];
__device__ int   d_deg[MAXN];      // zero at load; k_scan re-zeroes after use
__device__ int   d_off[MAXN + 1];
__device__ int   d_cur[MAXN];
__device__ int   d_ssrc[MAXE];

// ---------------- hist (+ block0 computes wsrc/wdst = W2 @ att2) ----------
__global__ void k_hist(const int* __restrict__ ei, int E, int vec,
                       const float* __restrict__ W2,
                       const float* __restrict__ as2v, const float* __restrict__ ad2v) {
    if (blockIdx.x == 0 && threadIdx.x < 128) {
        int k = threadIdx.x & 63;
        const float* att = (threadIdx.x < 64) ? as2v : ad2v;
        float s = 0.f;
#pragma unroll 16
        for (int c = 0; c < 128; c++) s += W2[k * 128 + c] * att[c];
        if (threadIdx.x < 64) d_wsrc[k] = s;
        else                  d_wdst[k] = s;
    }
    int i = blockIdx.x * blockDim.x + threadIdx.x;
    int e = i * 4;
    if (e >= E) return;
    if (vec && e + 3 < E) {
        int4 d = *(const int4*)(ei + E + e);
        atomicAdd(&d_deg[d.x], 1);
        atomicAdd(&d_deg[d.y], 1);
        atomicAdd(&d_deg[d.z], 1);
        atomicAdd(&d_deg[d.w], 1);
    } else {
        for (int j = e; j < E && j < e + 4; j++)
            atomicAdd(&d_deg[ei[E + j]], 1);
    }
}

// single-block scan; places self loop at slot 0; re-zeroes d_deg
__global__ __launch_bounds__(1024) void k_scan(int n) {
    __shared__ int warpsum[32];
    int t = threadIdx.x, lane = t & 31, wid = t >> 5;
    int ipt = (n + 1023) >> 10;
    int start = t * ipt;
    int endi  = min(start + ipt, n);
    int s = 0;
    for (int i = start; i < endi; i++) s += d_deg[i] + 1;
    int incl = s;
#pragma unroll
    for (int o = 1; o < 32; o <<= 1) {
        int v = __shfl_up_sync(0xffffffffu, incl, o);
        if (lane >= o) incl += v;
    }
    if (lane == 31) warpsum[wid] = incl;
    __syncthreads();
    if (wid == 0) {
        int v = warpsum[lane];
        int wi = v;
#pragma unroll
        for (int o = 1; o < 32; o <<= 1) {
            int u = __shfl_up_sync(0xffffffffu, wi, o);
            if (lane >= o) wi += u;
        }
        warpsum[lane] = wi - v;
    }
    __syncthreads();
    int run = warpsum[wid] + (incl - s);
    for (int i = start; i < endi; i++) {
        int d = d_deg[i];
        d_deg[i] = 0;
        d_off[i]  = run;
        d_ssrc[run] = i;
        d_cur[i]  = run + 1;
        run += d + 1;
    }
    if (t == 1023) d_off[n] = run;
}

// ------------- Fused Layer-1 GEMM + scatter (scatter-first layout) --------
// blocks [0, nsc): scatter, 16 edges/thread (two 8-wide MLP batches).
// blocks [nsc, G): gemm, grid-stride over row tiles.
// Scatter blocks co-reside with gemm wave 1, retire early, free the machine.
__global__ __launch_bounds__(256) void k_gemm1_scatter(
    const float* __restrict__ x, const float* __restrict__ W1,
    const float* __restrict__ as, const float* __restrict__ ad, int n,
    const int* __restrict__ ei, int E, int vec, int nsc)
{
    __shared__ float2 Ws[128 * 32];
    __shared__ float atts[64], attd[64];
    int t = threadIdx.x;

    if (blockIdx.x < nsc) {
        int i = blockIdx.x * blockDim.x + t;
        int e = i * 16;
        if (e >= E) return;
#pragma unroll
        for (int half = 0; half < 2; half++) {
            int eb = e + half * 8;
            if (eb >= E) break;
            if (vec && eb + 7 < E) {
                int4 s0 = *(const int4*)(ei + eb);
                int4 s1 = *(const int4*)(ei + eb + 4);
                int4 d0 = *(const int4*)(ei + E + eb);
                int4 d1 = *(const int4*)(ei + E + eb + 4);
                int p0 = atomicAdd(&d_cur[d0.x], 1);
                int p1 = atomicAdd(&d_cur[d0.y], 1);
                int p2 = atomicAdd(&d_cur[d0.z], 1);
                int p3 = atomicAdd(&d_cur[d0.w], 1);
                int p4 = atomicAdd(&d_cur[d1.x], 1);
                int p5 = atomicAdd(&d_cur[d1.y], 1);
                int p6 = atomicAdd(&d_cur[d1.z], 1);
                int p7 = atomicAdd(&d_cur[d1.w], 1);
                d_ssrc[p0] = s0.x; d_ssrc[p1] = s0.y;
                d_ssrc[p2] = s0.z; d_ssrc[p3] = s0.w;
                d_ssrc[p4] = s1.x; d_ssrc[p5] = s1.y;
                d_ssrc[p6] = s1.z; d_ssrc[p7] = s1.w;
            } else {
                for (int j = eb; j < E && j < eb + 8; j++)
                    d_ssrc[atomicAdd(&d_cur[ei[E + j]], 1)] = ei[j];
            }
        }
        return;
    }

    int w = t >> 5, l = t & 31;
    int nblk = gridDim.x - nsc;
    int bid  = blockIdx.x - nsc;
    const float2* Wv = (const float2*)W1;
    for (int i = t; i < 4096; i += 256) Ws[i] = Wv[i];
    if (t < 64) { atts[t] = as[t]; attd[t] = ad[t]; }
    __syncthreads();
    int ntiles = (n + 3) >> 2;
    for (int tile = bid * 8 + w; tile < ntiles; tile += nblk * 8) {
        int row0 = tile * 4;
        float xr[4][4];
#pragma unroll
        for (int r = 0; r < 4; r++) {
            const float* xp = x + (size_t)min(row0 + r, n - 1) * 128;
#pragma unroll
            for (int c = 0; c < 4; c++) xr[r][c] = xp[l + 32 * c];
        }
        float2 acc[4] = {{0,0},{0,0},{0,0},{0,0}};
#pragma unroll
        for (int c = 0; c < 4; c++) {
#pragma unroll 8
            for (int kk = 0; kk < 32; kk++) {
                float2 wv = Ws[(c * 32 + kk) * 32 + l];
#pragma unroll
                for (int r = 0; r < 4; r++) {
                    float xv = __shfl_sync(0xffffffffu, xr[r][c], kk);
                    acc[r].x += xv * wv.x;
                    acc[r].y += xv * wv.y;
                }
            }
        }
#pragma unroll
        for (int r = 0; r < 4; r++) {
            int row = row0 + r;
            if (row >= n) break;
            ((float2*)(d_h1 + (size_t)row * 64))[l] = acc[r];
            float ps = acc[r].x * atts[2 * l] + acc[r].y * atts[2 * l + 1];
            float pd = acc[r].x * attd[2 * l] + acc[r].y * attd[2 * l + 1];
            ps += __shfl_xor_sync(0xffffffffu, ps, 1);
            ps += __shfl_xor_sync(0xffffffffu, ps, 2);
            pd += __shfl_xor_sync(0xffffffffu, pd, 1);
            pd += __shfl_xor_sync(0xffffffffu, pd, 2);
            if ((l & 3) == 0) {
                d_as1[row * 8 + (l >> 2)] = ps;
                d_ad1[row * 8 + (l >> 2)] = pd;
            }
        }
    }
}

// --------------------------- Layer 1 aggregate ---------------------------
// Persistent warps (measured best: 58.7us); lane l owns channels 2l,2l+1.
__global__ __launch_bounds__(256) void k_agg1(const float* __restrict__ bias1, int n) {
    int t = threadIdx.x, w = t >> 5, l = t & 31;
    int hl = l >> 2;
    int gw = blockIdx.x * 8 + w;
    int nw = gridDim.x * 8;
    for (int node = gw; node < n; node += nw) {
        float adv = d_ad1[node * 8 + (l & 7)];
        int beg = d_off[node], end = d_off[node + 1];
        float acc0 = 0.f, acc1 = 0.f, dloc = 0.f;
        for (int ch = beg; ch < end; ch += 32) {
            int cnt = end - ch;
            int idx = d_ssrc[min(ch + l, end - 1)];
            float ec[8];
#pragma unroll
            for (int g = 0; g < 8; g++) {
                int ka = g * 4 + (l >> 3);
                int sA = __shfl_sync(0xffffffffu, idx, g * 4 + (l >> 3));
                float e = 0.f;
                if (ka < cnt) {
                    float al = __ldg(&d_as1[sA * 8 + (l & 7)]) + adv;
                    al = (al >= 0.f) ? al : 0.2f * al;
                    e = __expf(al);
                }
                ec[g] = e;
                dloc += e;
            }
#pragma unroll
            for (int g8 = 0; g8 < 4; g8++) {
                if (g8 * 8 >= cnt) break;
                int sj[8];
#pragma unroll
                for (int j = 0; j < 8; j++)
                    sj[j] = __shfl_sync(0xffffffffu, idx, g8 * 8 + j);
                float2 hj[8];
#pragma unroll
                for (int j = 0; j < 8; j++)
                    hj[j] = ((const float2*)(d_h1 + (size_t)sj[j] * 64))[l];
                float ev[8];
#pragma unroll
                for (int j = 0; j < 8; j++)
                    ev[j] = __shfl_sync(0xffffffffu, ec[g8 * 2 + (j >> 2)], (j & 3) * 8 + hl);
#pragma unroll
                for (int j = 0; j < 8; j++) {
                    acc0 += ev[j] * hj[j].x;
                    acc1 += ev[j] * hj[j].y;
                }
            }
        }
        dloc += __shfl_xor_sync(0xffffffffu, dloc, 8);
        dloc += __shfl_xor_sync(0xffffffffu, dloc, 16);
        float dsum = __shfl_sync(0xffffffffu, dloc, hl);
        float inv = 1.f / (dsum + 1e-16f);
        float o0 = acc0 * inv + bias1[2 * l];
        float o1 = acc1 * inv + bias1[2 * l + 1];
        o0 = (o0 > 0.f) ? o0 : expm1f(o0);
        o1 = (o1 > 0.f) ? o1 : expm1f(o1);
        ((float2*)(d_x1 + (size_t)node * 64))[l] = make_float2(o0, o1);
        float ss = o0 * d_wsrc[2 * l] + o1 * d_wsrc[2 * l + 1];
        float sd = o0 * d_wdst[2 * l] + o1 * d_wdst[2 * l + 1];
#pragma unroll
        for (int o = 16; o; o >>= 1) {
            ss += __shfl_xor_sync(0xffffffffu, ss, o);
            sd += __shfl_xor_sync(0xffffffffu, sd, o);
        }
        if (l == 0) { d_as2[node] = ss; d_ad2[node] = sd; }
    }
}

// --------------------------- Layer 2 aggregate ---------------------------
// NON-persistent (one node per warp, dynamic CTA dispatch = free balancing).
__global__ __launch_bounds__(256) void k_agg2(int n) {
    int t = threadIdx.x, w = t >> 5, l = t & 31;
    int node = blockIdx.x * 8 + w;
    if (node >= n) return;
    float adv = d_ad2[node];
    int beg = d_off[node], end = d_off[node + 1];
    float a0 = 0.f, a1 = 0.f, dpart = 0.f;
    for (int ch = beg; ch < end; ch += 32) {
        int cnt = end - ch;
        int idx = d_ssrc[min(ch + l, end - 1)];
        float e = 0.f;
        if (l < cnt) {
            float al = __ldg(&d_as2[idx]) + adv;
            al = (al >= 0.f) ? al : 0.2f * al;
            e = __expf(al);
            dpart += e;
        }
#pragma unroll
        for (int g8 = 0; g8 < 4; g8++) {
            if (g8 * 8 >= cnt) break;
            int sj[8];
            float ej[8];
#pragma unroll
            for (int j = 0; j < 8; j++) {
                sj[j] = __shfl_sync(0xffffffffu, idx, g8 * 8 + j);
                ej[j] = __shfl_sync(0xffffffffu, e,   g8 * 8 + j);
            }
            float2 hj[8];
#pragma unroll
            for (int j = 0; j < 8; j++)
                hj[j] = ((const float2*)(d_x1 + (size_t)sj[j] * 64))[l];
#pragma unroll
            for (int j = 0; j < 8; j++) {
                a0 += ej[j] * hj[j].x;
                a1 += ej[j] * hj[j].y;
            }
        }
    }
#pragma unroll
    for (int o = 16; o; o >>= 1) dpart += __shfl_xor_sync(0xffffffffu, dpart, o);
    float inv = 1.f / (dpart + 1e-16f);
    ((float2*)(d_z + (size_t)node * 64))[l] = make_float2(a0 * inv, a1 * inv);
}

// ---------------------- Final GEMM: out = z @ W2 + b2 --------------------
__global__ __launch_bounds__(256) void k_gemmF(
    const float* __restrict__ W2, const float* __restrict__ bias2,
    float* __restrict__ out, int n)
{
    __shared__ float4 Ws[64 * 32];
    __shared__ float4 bs[32];
    int t = threadIdx.x, w = t >> 5, l = t & 31;
    const float4* Wv = (const float4*)W2;
    for (int i = t; i < 2048; i += 256) Ws[i] = Wv[i];
    if (t < 32) bs[t] = ((const float4*)bias2)[t];
    __syncthreads();
    int ntiles = (n + 3) >> 2;
    for (int tile = blockIdx.x * 8 + w; tile < ntiles; tile += gridDim.x * 8) {
        int row0 = tile * 4;
        float xr[4][2];
#pragma unroll
        for (int r = 0; r < 4; r++) {
            const float* xp = d_z + (size_t)min(row0 + r, n - 1) * 64;
#pragma unroll
            for (int c = 0; c < 2; c++) xr[r][c] = xp[l + 32 * c];
        }
        float4 acc[4] = {{0,0,0,0},{0,0,0,0},{0,0,0,0},{0,0,0,0}};
#pragma unroll
        for (int c = 0; c < 2; c++) {
#pragma unroll 8
            for (int kk = 0; kk < 32; kk++) {
                float4 wv = Ws[(c * 32 + kk) * 32 + l];
#pragma unroll
                for (int r = 0; r < 4; r++) {
                    float xv = __shfl_sync(0xffffffffu, xr[r][c], kk);
                    acc[r].x += xv * wv.x; acc[r].y += xv * wv.y;
                    acc[r].z += xv * wv.z; acc[r].w += xv * wv.w;
                }
            }
        }
        float4 b = bs[l];
#pragma unroll
        for (int r = 0; r < 4; r++) {
            int row = row0 + r;
            if (row >= n) break;
            ((float4*)(out + (size_t)row * 128))[l] =
                make_float4(acc[r].x + b.x, acc[r].y + b.y,
                            acc[r].z + b.z, acc[r].w + b.w);
        }
    }
}

// ------------------------------- launch ----------------------------------
extern "C" void kernel_launch(void* const* d_in, const int* in_sizes, int n_in,
                              void* d_out, int out_size)
{
    const float* x    = (const float*)d_in[0];
    const int*   ei   = (const int*)d_in[1];
    const float* W1   = (const float*)d_in[2];
    const float* asr1 = (const float*)d_in[3];
    const float* ads1 = (const float*)d_in[4];
    const float* b1   = (const float*)d_in[5];
    const float* W2   = (const float*)d_in[6];
    const float* asr2 = (const float*)d_in[7];
    const float* ads2 = (const float*)d_in[8];
    const float* b2   = (const float*)d_in[9];
    float* out = (float*)d_out;

    int N  = in_sizes[0] / 128;
    int E  = in_sizes[1] / 2;
    int vec = ((E & 3) == 0) ? 1 : 0;
    int e4  = (E + 3) / 4;
    int e16 = (E + 15) / 16;

    k_hist<<<(e4 + 255) / 256, 256>>>(ei, E, vec, W2, asr2, ads2);
    k_scan<<<1, 1024>>>(N);

    int ntb = ((N + 3) / 4 + 7) / 8;              // gemm blocks (1563)
    int nsc = (e16 + 255) / 256;                  // scatter blocks (~391)
    k_gemm1_scatter<<<nsc + ntb, 256>>>(x, W1, asr1, ads1, N, ei, E, vec, nsc);

    k_agg1<<<1184, 256>>>(b1, N);
    k_agg2<<<(N + 7) / 8, 256>>>(N);
    k_gemmF<<<ntb, 256>>>(W2, b2, out, N);
}

// round 14
// speedup vs baseline: 1.0706x; 1.0706x over previous
#include <cuda_runtime.h>
#include <math.h>

#define MAXN 50048
#define MAXE 1650080

// ------------ static device scratch (zero-initialized at load) -----------
__device__ float d_h1[MAXN * 64];
__device__ float d_as1[MAXN * 8];
__device__ float d_ad1[MAXN * 8];
__device__ float d_x1[MAXN * 64];
__device__ float d_z[MAXN * 64];
__device__ float d_as2[MAXN];
__device__ float d_ad2[MAXN];
__device__ float d_wsrc[64];
__device__ float d_wdst[64];
__device__ int   d_deg[MAXN];      // zero at load; k_scan re-zeroes after use
__device__ int   d_off[MAXN + 1];
__device__ int   d_cur[MAXN];
__device__ int   d_ssrc[MAXE];

// ---------------- hist (+ block0 computes wsrc/wdst = W2 @ att2) ----------
__global__ void k_hist(const int* __restrict__ ei, int E, int vec,
                       const float* __restrict__ W2,
                       const float* __restrict__ as2v, const float* __restrict__ ad2v) {
    if (blockIdx.x == 0 && threadIdx.x < 128) {
        int k = threadIdx.x & 63;
        const float* att = (threadIdx.x < 64) ? as2v : ad2v;
        float s = 0.f;
#pragma unroll 16
        for (int c = 0; c < 128; c++) s += W2[k * 128 + c] * att[c];
        if (threadIdx.x < 64) d_wsrc[k] = s;
        else                  d_wdst[k] = s;
    }
    int i = blockIdx.x * blockDim.x + threadIdx.x;
    int e = i * 4;
    if (e >= E) return;
    if (vec && e + 3 < E) {
        int4 d = *(const int4*)(ei + E + e);
        atomicAdd(&d_deg[d.x], 1);
        atomicAdd(&d_deg[d.y], 1);
        atomicAdd(&d_deg[d.z], 1);
        atomicAdd(&d_deg[d.w], 1);
    } else {
        for (int j = e; j < E && j < e + 4; j++)
            atomicAdd(&d_deg[ei[E + j]], 1);
    }
}

// single-block scan; places self loop at slot 0; re-zeroes d_deg
__global__ __launch_bounds__(1024) void k_scan(int n) {
    __shared__ int warpsum[32];
    int t = threadIdx.x, lane = t & 31, wid = t >> 5;
    int ipt = (n + 1023) >> 10;
    int start = t * ipt;
    int endi  = min(start + ipt, n);
    int s = 0;
    for (int i = start; i < endi; i++) s += d_deg[i] + 1;
    int incl = s;
#pragma unroll
    for (int o = 1; o < 32; o <<= 1) {
        int v = __shfl_up_sync(0xffffffffu, incl, o);
        if (lane >= o) incl += v;
    }
    if (lane == 31) warpsum[wid] = incl;
    __syncthreads();
    if (wid == 0) {
        int v = warpsum[lane];
        int wi = v;
#pragma unroll
        for (int o = 1; o < 32; o <<= 1) {
            int u = __shfl_up_sync(0xffffffffu, wi, o);
            if (lane >= o) wi += u;
        }
        warpsum[lane] = wi - v;
    }
    __syncthreads();
    int run = warpsum[wid] + (incl - s);
    for (int i = start; i < endi; i++) {
        int d = d_deg[i];
        d_deg[i] = 0;
        d_off[i]  = run;
        d_ssrc[run] = i;
        d_cur[i]  = run + 1;
        run += d + 1;
    }
    if (t == 1023) d_off[n] = run;
}

// ------------- Fused Layer-1 GEMM + scatter (interleaved roles) -----------
// even blocks: gemm (grid-stride); odd blocks: scatter, 4 edges/thread.
__global__ __launch_bounds__(256) void k_gemm1_scatter(
    const float* __restrict__ x, const float* __restrict__ W1,
    const float* __restrict__ as, const float* __restrict__ ad, int n,
    const int* __restrict__ ei, int E, int vec)
{
    __shared__ float2 Ws[128 * 32];
    __shared__ float atts[64], attd[64];
    int t = threadIdx.x;

    if (blockIdx.x & 1) {
        int i = (blockIdx.x >> 1) * blockDim.x + t;
        int e = i * 4;
        if (e >= E) return;
        if (vec && e + 3 < E) {
            int4 s = *(const int4*)(ei + e);
            int4 d = *(const int4*)(ei + E + e);
            d_ssrc[atomicAdd(&d_cur[d.x], 1)] = s.x;
            d_ssrc[atomicAdd(&d_cur[d.y], 1)] = s.y;
            d_ssrc[atomicAdd(&d_cur[d.z], 1)] = s.z;
            d_ssrc[atomicAdd(&d_cur[d.w], 1)] = s.w;
        } else {
            for (int j = e; j < E && j < e + 4; j++)
                d_ssrc[atomicAdd(&d_cur[ei[E + j]], 1)] = ei[j];
        }
        return;
    }

    int w = t >> 5, l = t & 31;
    int nblk = gridDim.x >> 1;
    int bid  = blockIdx.x >> 1;
    const float2* Wv = (const float2*)W1;
    for (int i = t; i < 4096; i += 256) Ws[i] = Wv[i];
    if (t < 64) { atts[t] = as[t]; attd[t] = ad[t]; }
    __syncthreads();
    int ntiles = (n + 3) >> 2;
    for (int tile = bid * 8 + w; tile < ntiles; tile += nblk * 8) {
        int row0 = tile * 4;
        float xr[4][4];
#pragma unroll
        for (int r = 0; r < 4; r++) {
            const float* xp = x + (size_t)min(row0 + r, n - 1) * 128;
#pragma unroll
            for (int c = 0; c < 4; c++) xr[r][c] = xp[l + 32 * c];
        }
        float2 acc[4] = {{0,0},{0,0},{0,0},{0,0}};
#pragma unroll
        for (int c = 0; c < 4; c++) {
#pragma unroll 8
            for (int kk = 0; kk < 32; kk++) {
                float2 wv = Ws[(c * 32 + kk) * 32 + l];
#pragma unroll
                for (int r = 0; r < 4; r++) {
                    float xv = __shfl_sync(0xffffffffu, xr[r][c], kk);
                    acc[r].x += xv * wv.x;
                    acc[r].y += xv * wv.y;
                }
            }
        }
#pragma unroll
        for (int r = 0; r < 4; r++) {
            int row = row0 + r;
            if (row >= n) break;
            ((float2*)(d_h1 + (size_t)row * 64))[l] = acc[r];
            float ps = acc[r].x * atts[2 * l] + acc[r].y * atts[2 * l + 1];
            float pd = acc[r].x * attd[2 * l] + acc[r].y * attd[2 * l + 1];
            ps += __shfl_xor_sync(0xffffffffu, ps, 1);
            ps += __shfl_xor_sync(0xffffffffu, ps, 2);
            pd += __shfl_xor_sync(0xffffffffu, pd, 1);
            pd += __shfl_xor_sync(0xffffffffu, pd, 2);
            if ((l & 3) == 0) {
                d_as1[row * 8 + (l >> 2)] = ps;
                d_ad1[row * 8 + (l >> 2)] = pd;
            }
        }
    }
}

// --------------------------- Layer 1 aggregate ---------------------------
// Persistent warps + lane-local denominator (measured best form: 58.7us).
__global__ __launch_bounds__(256) void k_agg1(const float* __restrict__ bias1, int n) {
    int t = threadIdx.x, w = t >> 5, l = t & 31;
    int hl = l >> 2;
    int gw = blockIdx.x * 8 + w;
    int nw = gridDim.x * 8;
    for (int node = gw; node < n; node += nw) {
        float adv = d_ad1[node * 8 + (l & 7)];
        int beg = d_off[node], end = d_off[node + 1];
        float acc0 = 0.f, acc1 = 0.f, dloc = 0.f;
        for (int ch = beg; ch < end; ch += 32) {
            int cnt = end - ch;
            int idx = d_ssrc[min(ch + l, end - 1)];
            float ec[8];
#pragma unroll
            for (int g = 0; g < 8; g++) {
                int ka = g * 4 + (l >> 3);
                int sA = __shfl_sync(0xffffffffu, idx, g * 4 + (l >> 3));
                float e = 0.f;
                if (ka < cnt) {
                    float al = __ldg(&d_as1[sA * 8 + (l & 7)]) + adv;
                    al = (al >= 0.f) ? al : 0.2f * al;
                    e = __expf(al);
                }
                ec[g] = e;
                dloc += e;
            }
#pragma unroll
            for (int g8 = 0; g8 < 4; g8++) {
                if (g8 * 8 >= cnt) break;
                int sj[8];
#pragma unroll
                for (int j = 0; j < 8; j++)
                    sj[j] = __shfl_sync(0xffffffffu, idx, g8 * 8 + j);
                float2 hj[8];
#pragma unroll
                for (int j = 0; j < 8; j++)
                    hj[j] = ((const float2*)(d_h1 + (size_t)sj[j] * 64))[l];
                float ev[8];
#pragma unroll
                for (int j = 0; j < 8; j++)
                    ev[j] = __shfl_sync(0xffffffffu, ec[g8 * 2 + (j >> 2)], (j & 3) * 8 + hl);
#pragma unroll
                for (int j = 0; j < 8; j++) {
                    acc0 += ev[j] * hj[j].x;
                    acc1 += ev[j] * hj[j].y;
                }
            }
        }
        dloc += __shfl_xor_sync(0xffffffffu, dloc, 8);
        dloc += __shfl_xor_sync(0xffffffffu, dloc, 16);
        float dsum = __shfl_sync(0xffffffffu, dloc, hl);
        float inv = 1.f / (dsum + 1e-16f);
        float o0 = acc0 * inv + bias1[2 * l];
        float o1 = acc1 * inv + bias1[2 * l + 1];
        o0 = (o0 > 0.f) ? o0 : expm1f(o0);
        o1 = (o1 > 0.f) ? o1 : expm1f(o1);
        ((float2*)(d_x1 + (size_t)node * 64))[l] = make_float2(o0, o1);
        float ss = o0 * d_wsrc[2 * l] + o1 * d_wsrc[2 * l + 1];
        float sd = o0 * d_wdst[2 * l] + o1 * d_wdst[2 * l + 1];
#pragma unroll
        for (int o = 16; o; o >>= 1) {
            ss += __shfl_xor_sync(0xffffffffu, ss, o);
            sd += __shfl_xor_sync(0xffffffffu, sd, o);
        }
        if (l == 0) { d_as2[node] = ss; d_ad2[node] = sd; }
    }
}

// --------------------------- Layer 2 aggregate ---------------------------
// NON-persistent (R7 measured-best form): one node per warp, float2 gathers.
__global__ __launch_bounds__(256) void k_agg2(int n) {
    int t = threadIdx.x, w = t >> 5, l = t & 31;
    int node = blockIdx.x * 8 + w;
    if (node >= n) return;
    float adv = d_ad2[node];
    int beg = d_off[node], end = d_off[node + 1];
    float a0 = 0.f, a1 = 0.f, dpart = 0.f;
    for (int ch = beg; ch < end; ch += 32) {
        int cnt = end - ch;
        int idx = d_ssrc[min(ch + l, end - 1)];
        float e = 0.f;
        if (l < cnt) {
            float al = __ldg(&d_as2[idx]) + adv;
            al = (al >= 0.f) ? al : 0.2f * al;
            e = __expf(al);
            dpart += e;
        }
#pragma unroll
        for (int g8 = 0; g8 < 4; g8++) {
            if (g8 * 8 >= cnt) break;
            int sj[8];
            float ej[8];
#pragma unroll
            for (int j = 0; j < 8; j++) {
                sj[j] = __shfl_sync(0xffffffffu, idx, g8 * 8 + j);
                ej[j] = __shfl_sync(0xffffffffu, e,   g8 * 8 + j);
            }
            float2 hj[8];
#pragma unroll
            for (int j = 0; j < 8; j++)
                hj[j] = ((const float2*)(d_x1 + (size_t)sj[j] * 64))[l];
#pragma unroll
            for (int j = 0; j < 8; j++) {
                a0 += ej[j] * hj[j].x;
                a1 += ej[j] * hj[j].y;
            }
        }
    }
#pragma unroll
    for (int o = 16; o; o >>= 1) dpart += __shfl_xor_sync(0xffffffffu, dpart, o);
    float inv = 1.f / (dpart + 1e-16f);
    ((float2*)(d_z + (size_t)node * 64))[l] = make_float2(a0 * inv, a1 * inv);
}

// ---------------------- Final GEMM: out = z @ W2 + b2 --------------------
__global__ __launch_bounds__(256) void k_gemmF(
    const float* __restrict__ W2, const float* __restrict__ bias2,
    float* __restrict__ out, int n)
{
    __shared__ float4 Ws[64 * 32];
    __shared__ float4 bs[32];
    int t = threadIdx.x, w = t >> 5, l = t & 31;
    const float4* Wv = (const float4*)W2;
    for (int i = t; i < 2048; i += 256) Ws[i] = Wv[i];
    if (t < 32) bs[t] = ((const float4*)bias2)[t];
    __syncthreads();
    int ntiles = (n + 3) >> 2;
    for (int tile = blockIdx.x * 8 + w; tile < ntiles; tile += gridDim.x * 8) {
        int row0 = tile * 4;
        float xr[4][2];
#pragma unroll
        for (int r = 0; r < 4; r++) {
            const float* xp = d_z + (size_t)min(row0 + r, n - 1) * 64;
#pragma unroll
            for (int c = 0; c < 2; c++) xr[r][c] = xp[l + 32 * c];
        }
        float4 acc[4] = {{0,0,0,0},{0,0,0,0},{0,0,0,0},{0,0,0,0}};
#pragma unroll
        for (int c = 0; c < 2; c++) {
#pragma unroll 8
            for (int kk = 0; kk < 32; kk++) {
                float4 wv = Ws[(c * 32 + kk) * 32 + l];
#pragma unroll
                for (int r = 0; r < 4; r++) {
                    float xv = __shfl_sync(0xffffffffu, xr[r][c], kk);
                    acc[r].x += xv * wv.x; acc[r].y += xv * wv.y;
                    acc[r].z += xv * wv.z; acc[r].w += xv * wv.w;
                }
            }
        }
        float4 b = bs[l];
#pragma unroll
        for (int r = 0; r < 4; r++) {
            int row = row0 + r;
            if (row >= n) break;
            ((float4*)(out + (size_t)row * 128))[l] =
                make_float4(acc[r].x + b.x, acc[r].y + b.y,
                            acc[r].z + b.z, acc[r].w + b.w);
        }
    }
}

// ------------------------------- launch ----------------------------------
extern "C" void kernel_launch(void* const* d_in, const int* in_sizes, int n_in,
                              void* d_out, int out_size)
{
    const float* x    = (const float*)d_in[0];
    const int*   ei   = (const int*)d_in[1];
    const float* W1   = (const float*)d_in[2];
    const float* asr1 = (const float*)d_in[3];
    const float* ads1 = (const float*)d_in[4];
    const float* b1   = (const float*)d_in[5];
    const float* W2   = (const float*)d_in[6];
    const float* asr2 = (const float*)d_in[7];
    const float* ads2 = (const float*)d_in[8];
    const float* b2   = (const float*)d_in[9];
    float* out = (float*)d_out;

    int N  = in_sizes[0] / 128;
    int E  = in_sizes[1] / 2;
    int vec = ((E & 3) == 0) ? 1 : 0;
    int e4 = (E + 3) / 4;

    k_hist<<<(e4 + 255) / 256, 256>>>(ei, E, vec, W2, asr2, ads2);
    k_scan<<<1, 1024>>>(N);

    int ntb = ((N + 3) / 4 + 7) / 8;
    int sb  = (e4 + 255) / 256;
    int G   = 2 * (ntb > sb ? ntb : sb);
    k_gemm1_scatter<<<G, 256>>>(x, W1, asr1, ads1, N, ei, E, vec);

    k_agg1<<<1184, 256>>>(b1, N);
    k_agg2<<<(N + 7) / 8, 256>>>(N);
    k_gemmF<<<ntb, 256>>>(W2, b2, out, N);
}

// round 16
// speedup vs baseline: 1.0714x; 1.0008x over previous
#include <cuda_runtime.h>
#include <math.h>
#include <stdint.h>

#define MAXN 50048
#define MAXE 1650080

// ------------ static device scratch (zero-initialized at load) -----------
__device__ float d_h1[MAXN * 64];
__device__ float d_as1[MAXN * 8];
__device__ float d_ad1[MAXN * 8];
__device__ float d_x1[MAXN * 64];
__device__ float d_z[MAXN * 64];
__device__ float d_as2[MAXN];
__device__ float d_ad2[MAXN];
__device__ float d_wsrc[64];
__device__ float d_wdst[64];
__device__ int   d_deg[MAXN];      // zero at load; k_scan re-zeroes after use
__device__ int   d_off[MAXN + 1];
__device__ int   d_cur[MAXN];
__device__ int   d_ssrc[MAXE];

// ---------------- hist (+ block0 computes wsrc/wdst = W2 @ att2) ----------
__global__ void k_hist(const int* __restrict__ ei, int E, int vec,
                       const float* __restrict__ W2,
                       const float* __restrict__ as2v, const float* __restrict__ ad2v) {
    if (blockIdx.x == 0 && threadIdx.x < 128) {
        int k = threadIdx.x & 63;
        const float* att = (threadIdx.x < 64) ? as2v : ad2v;
        float s = 0.f;
#pragma unroll 16
        for (int c = 0; c < 128; c++) s += W2[k * 128 + c] * att[c];
        if (threadIdx.x < 64) d_wsrc[k] = s;
        else                  d_wdst[k] = s;
    }
    int i = blockIdx.x * blockDim.x + threadIdx.x;
    int e = i * 4;
    if (e >= E) return;
    if (vec && e + 3 < E) {
        int4 d = *(const int4*)(ei + E + e);
        atomicAdd(&d_deg[d.x], 1);
        atomicAdd(&d_deg[d.y], 1);
        atomicAdd(&d_deg[d.z], 1);
        atomicAdd(&d_deg[d.w], 1);
    } else {
        for (int j = e; j < E && j < e + 4; j++)
            atomicAdd(&d_deg[ei[E + j]], 1);
    }
}

// single-block scan; places self loop at slot 0; re-zeroes d_deg
__global__ __launch_bounds__(1024) void k_scan(int n) {
    __shared__ int warpsum[32];
    int t = threadIdx.x, lane = t & 31, wid = t >> 5;
    int ipt = (n + 1023) >> 10;
    int start = t * ipt;
    int endi  = min(start + ipt, n);
    int s = 0;
    for (int i = start; i < endi; i++) s += d_deg[i] + 1;
    int incl = s;
#pragma unroll
    for (int o = 1; o < 32; o <<= 1) {
        int v = __shfl_up_sync(0xffffffffu, incl, o);
        if (lane >= o) incl += v;
    }
    if (lane == 31) warpsum[wid] = incl;
    __syncthreads();
    if (wid == 0) {
        int v = warpsum[lane];
        int wi = v;
#pragma unroll
        for (int o = 1; o < 32; o <<= 1) {
            int u = __shfl_up_sync(0xffffffffu, wi, o);
            if (lane >= o) wi += u;
        }
        warpsum[lane] = wi - v;
    }
    __syncthreads();
    int run = warpsum[wid] + (incl - s);
    for (int i = start; i < endi; i++) {
        int d = d_deg[i];
        d_deg[i] = 0;
        d_off[i]  = run;
        d_ssrc[run] = i;
        d_cur[i]  = run + 1;
        run += d + 1;
    }
    if (t == 1023) d_off[n] = run;
}

// ------------- Fused Layer-1 GEMM + scatter (interleaved roles) -----------
__global__ __launch_bounds__(256) void k_gemm1_scatter(
    const float* __restrict__ x, const float* __restrict__ W1,
    const float* __restrict__ as, const float* __restrict__ ad, int n,
    const int* __restrict__ ei, int E, int vec)
{
    __shared__ float2 Ws[128 * 32];
    __shared__ float atts[64], attd[64];
    int t = threadIdx.x;

    if (blockIdx.x & 1) {
        int i = (blockIdx.x >> 1) * blockDim.x + t;
        int e = i * 4;
        if (e >= E) return;
        if (vec && e + 3 < E) {
            int4 s = *(const int4*)(ei + e);
            int4 d = *(const int4*)(ei + E + e);
            d_ssrc[atomicAdd(&d_cur[d.x], 1)] = s.x;
            d_ssrc[atomicAdd(&d_cur[d.y], 1)] = s.y;
            d_ssrc[atomicAdd(&d_cur[d.z], 1)] = s.z;
            d_ssrc[atomicAdd(&d_cur[d.w], 1)] = s.w;
        } else {
            for (int j = e; j < E && j < e + 4; j++)
                d_ssrc[atomicAdd(&d_cur[ei[E + j]], 1)] = ei[j];
        }
        return;
    }

    int w = t >> 5, l = t & 31;
    int nblk = gridDim.x >> 1;
    int bid  = blockIdx.x >> 1;
    const float2* Wv = (const float2*)W1;
    for (int i = t; i < 4096; i += 256) Ws[i] = Wv[i];
    if (t < 64) { atts[t] = as[t]; attd[t] = ad[t]; }
    __syncthreads();
    int ntiles = (n + 3) >> 2;
    for (int tile = bid * 8 + w; tile < ntiles; tile += nblk * 8) {
        int row0 = tile * 4;
        float xr[4][4];
#pragma unroll
        for (int r = 0; r < 4; r++) {
            const float* xp = x + (size_t)min(row0 + r, n - 1) * 128;
#pragma unroll
            for (int c = 0; c < 4; c++) xr[r][c] = xp[l + 32 * c];
        }
        float2 acc[4] = {{0,0},{0,0},{0,0},{0,0}};
#pragma unroll
        for (int c = 0; c < 4; c++) {
#pragma unroll 8
            for (int kk = 0; kk < 32; kk++) {
                float2 wv = Ws[(c * 32 + kk) * 32 + l];
#pragma unroll
                for (int r = 0; r < 4; r++) {
                    float xv = __shfl_sync(0xffffffffu, xr[r][c], kk);
                    acc[r].x += xv * wv.x;
                    acc[r].y += xv * wv.y;
                }
            }
        }
#pragma unroll
        for (int r = 0; r < 4; r++) {
            int row = row0 + r;
            if (row >= n) break;
            ((float2*)(d_h1 + (size_t)row * 64))[l] = acc[r];
            float ps = acc[r].x * atts[2 * l] + acc[r].y * atts[2 * l + 1];
            float pd = acc[r].x * attd[2 * l] + acc[r].y * attd[2 * l + 1];
            ps += __shfl_xor_sync(0xffffffffu, ps, 1);
            ps += __shfl_xor_sync(0xffffffffu, ps, 2);
            pd += __shfl_xor_sync(0xffffffffu, pd, 1);
            pd += __shfl_xor_sync(0xffffffffu, pd, 2);
            if ((l & 3) == 0) {
                d_as1[row * 8 + (l >> 2)] = ps;
                d_ad1[row * 8 + (l >> 2)] = pd;
            }
        }
    }
}

// --------------------------- Layer 1 aggregate ---------------------------
// Persistent warps. Gather scheme: float4/lane, warp halves read edge
// pairs (lanes 0-15 -> even edge, 16-31 -> odd edge of each pair); one
// LDG.128 covers TWO edge rows. Lane owns channels 4*hl..4*hl+3 (hl=l&15,
// head=hl>>1). Halves merged by xor-16 at the end.
__global__ __launch_bounds__(256) void k_agg1(const float* __restrict__ bias1, int n) {
    int t = threadIdx.x, w = t >> 5, l = t & 31;
    int half = l >> 4, hl = l & 15, head = hl >> 1;
    const char* h1b = (const char*)d_h1;
    uint32_t coff = (uint32_t)hl * 16u;
    int gw = blockIdx.x * 8 + w;
    int nw = gridDim.x * 8;
    for (int node = gw; node < n; node += nw) {
        float adv = d_ad1[node * 8 + (l & 7)];
        int beg = d_off[node], end = d_off[node + 1];
        float4 acc = make_float4(0.f, 0.f, 0.f, 0.f);
        float dloc = 0.f;
        for (int ch = beg; ch < end; ch += 32) {
            int cnt = end - ch;
            int idx = d_ssrc[min(ch + l, end - 1)];
            float ec[8];                        // e for edge g*4+(l>>3), head l&7
#pragma unroll
            for (int g = 0; g < 8; g++) {
                int ka = g * 4 + (l >> 3);
                int sA = __shfl_sync(0xffffffffu, idx, g * 4 + (l >> 3));
                float e = 0.f;
                if (ka < cnt) {
                    float al = __ldg(&d_as1[sA * 8 + (l & 7)]) + adv;
                    al = (al >= 0.f) ? al : 0.2f * al;
                    e = __expf(al);
                }
                ec[g] = e;
                dloc += e;
            }
#pragma unroll
            for (int g8 = 0; g8 < 4; g8++) {
                if (g8 * 8 >= cnt) break;
                int sj[4];
#pragma unroll
                for (int j = 0; j < 4; j++)
                    sj[j] = __shfl_sync(0xffffffffu, idx, g8 * 8 + 2 * j + half);
                // e broadcast: edge E=g8*8+2j+half lives in ec[2*g8+(j>>1)],
                // source lane ((2j+half)&3)*8 + head  (register idx is uniform)
                float ej[4];
                ej[0] = __shfl_sync(0xffffffffu, ec[2 * g8],     ((0 + half) & 3) * 8 + head);
                ej[1] = __shfl_sync(0xffffffffu, ec[2 * g8],     ((2 + half) & 3) * 8 + head);
                ej[2] = __shfl_sync(0xffffffffu, ec[2 * g8 + 1], ((4 + half) & 3) * 8 + head);
                ej[3] = __shfl_sync(0xffffffffu, ec[2 * g8 + 1], ((6 + half) & 3) * 8 + head);
                float4 hj[4];
#pragma unroll
                for (int j = 0; j < 4; j++)
                    hj[j] = *(const float4*)(h1b + ((uint32_t)sj[j] * 256u + coff));
#pragma unroll
                for (int j = 0; j < 4; j++) {
                    acc.x += ej[j] * hj[j].x; acc.y += ej[j] * hj[j].y;
                    acc.z += ej[j] * hj[j].z; acc.w += ej[j] * hj[j].w;
                }
            }
        }
        // merge even-edge (half0) and odd-edge (half1) partials
        acc.x += __shfl_xor_sync(0xffffffffu, acc.x, 16);
        acc.y += __shfl_xor_sync(0xffffffffu, acc.y, 16);
        acc.z += __shfl_xor_sync(0xffffffffu, acc.z, 16);
        acc.w += __shfl_xor_sync(0xffffffffu, acc.w, 16);
        // denominator (exp-lane layout reduce)
        dloc += __shfl_xor_sync(0xffffffffu, dloc, 8);
        dloc += __shfl_xor_sync(0xffffffffu, dloc, 16);
        float dsum = __shfl_sync(0xffffffffu, dloc, head);
        float inv = 1.f / (dsum + 1e-16f);
        float4 b = ((const float4*)bias1)[hl];
        float o0 = acc.x * inv + b.x;
        float o1 = acc.y * inv + b.y;
        float o2 = acc.z * inv + b.z;
        float o3 = acc.w * inv + b.w;
        o0 = (o0 > 0.f) ? o0 : expm1f(o0);
        o1 = (o1 > 0.f) ? o1 : expm1f(o1);
        o2 = (o2 > 0.f) ? o2 : expm1f(o2);
        o3 = (o3 > 0.f) ? o3 : expm1f(o3);
        if (half == 0)
            ((float4*)(d_x1 + (size_t)node * 64))[hl] = make_float4(o0, o1, o2, o3);
        // layer-2 logits: x1 . wsrc / x1 . wdst (halves hold duplicates;
        // xor over 1,2,4,8 reduces each 16-lane half to the true total)
        float ss = o0 * d_wsrc[4 * hl]     + o1 * d_wsrc[4 * hl + 1]
                 + o2 * d_wsrc[4 * hl + 2] + o3 * d_wsrc[4 * hl + 3];
        float sd = o0 * d_wdst[4 * hl]     + o1 * d_wdst[4 * hl + 1]
                 + o2 * d_wdst[4 * hl + 2] + o3 * d_wdst[4 * hl + 3];
#pragma unroll
        for (int o = 8; o; o >>= 1) {
            ss += __shfl_xor_sync(0xffffffffu, ss, o);
            sd += __shfl_xor_sync(0xffffffffu, sd, o);
        }
        if (l == 0) { d_as2[node] = ss; d_ad2[node] = sd; }
    }
}

// --------------------------- Layer 2 aggregate ---------------------------
// Non-persistent; same float4 pair-gather scheme on x1 rows.
__global__ __launch_bounds__(256) void k_agg2(int n) {
    int t = threadIdx.x, w = t >> 5, l = t & 31;
    int half = l >> 4, hl = l & 15;
    const char* x1b = (const char*)d_x1;
    uint32_t coff = (uint32_t)hl * 16u;
    int node = blockIdx.x * 8 + w;
    if (node >= n) return;
    float adv = d_ad2[node];
    int beg = d_off[node], end = d_off[node + 1];
    float4 acc = make_float4(0.f, 0.f, 0.f, 0.f);
    float dpart = 0.f;
    for (int ch = beg; ch < end; ch += 32) {
        int cnt = end - ch;
        int idx = d_ssrc[min(ch + l, end - 1)];
        float e = 0.f;
        if (l < cnt) {
            float al = __ldg(&d_as2[idx]) + adv;
            al = (al >= 0.f) ? al : 0.2f * al;
            e = __expf(al);
            dpart += e;
        }
#pragma unroll
        for (int g8 = 0; g8 < 4; g8++) {
            if (g8 * 8 >= cnt) break;
            int sj[4];
            float ej[4];
#pragma unroll
            for (int j = 0; j < 4; j++) {
                sj[j] = __shfl_sync(0xffffffffu, idx, g8 * 8 + 2 * j + half);
                ej[j] = __shfl_sync(0xffffffffu, e,   g8 * 8 + 2 * j + half);
            }
            float4 hj[4];
#pragma unroll
            for (int j = 0; j < 4; j++)
                hj[j] = *(const float4*)(x1b + ((uint32_t)sj[j] * 256u + coff));
#pragma unroll
            for (int j = 0; j < 4; j++) {
                acc.x += ej[j] * hj[j].x; acc.y += ej[j] * hj[j].y;
                acc.z += ej[j] * hj[j].z; acc.w += ej[j] * hj[j].w;
            }
        }
    }
    acc.x += __shfl_xor_sync(0xffffffffu, acc.x, 16);
    acc.y += __shfl_xor_sync(0xffffffffu, acc.y, 16);
    acc.z += __shfl_xor_sync(0xffffffffu, acc.z, 16);
    acc.w += __shfl_xor_sync(0xffffffffu, acc.w, 16);
#pragma unroll
    for (int o = 16; o; o >>= 1) dpart += __shfl_xor_sync(0xffffffffu, dpart, o);
    float inv = 1.f / (dpart + 1e-16f);
    if (half == 0)
        ((float4*)(d_z + (size_t)node * 64))[hl] =
            make_float4(acc.x * inv, acc.y * inv, acc.z * inv, acc.w * inv);
}

// ---------------------- Final GEMM: out = z @ W2 + b2 --------------------
__global__ __launch_bounds__(256) void k_gemmF(
    const float* __restrict__ W2, const float* __restrict__ bias2,
    float* __restrict__ out, int n)
{
    __shared__ float4 Ws[64 * 32];
    __shared__ float4 bs[32];
    int t = threadIdx.x, w = t >> 5, l = t & 31;
    const float4* Wv = (const float4*)W2;
    for (int i = t; i < 2048; i += 256) Ws[i] = Wv[i];
    if (t < 32) bs[t] = ((const float4*)bias2)[t];
    __syncthreads();
    int ntiles = (n + 3) >> 2;
    for (int tile = blockIdx.x * 8 + w; tile < ntiles; tile += gridDim.x * 8) {
        int row0 = tile * 4;
        float xr[4][2];
#pragma unroll
        for (int r = 0; r < 4; r++) {
            const float* xp = d_z + (size_t)min(row0 + r, n - 1) * 64;
#pragma unroll
            for (int c = 0; c < 2; c++) xr[r][c] = xp[l + 32 * c];
        }
        float4 acc[4] = {{0,0,0,0},{0,0,0,0},{0,0,0,0},{0,0,0,0}};
#pragma unroll
        for (int c = 0; c < 2; c++) {
#pragma unroll 8
            for (int kk = 0; kk < 32; kk++) {
                float4 wv = Ws[(c * 32 + kk) * 32 + l];
#pragma unroll
                for (int r = 0; r < 4; r++) {
                    float xv = __shfl_sync(0xffffffffu, xr[r][c], kk);
                    acc[r].x += xv * wv.x; acc[r].y += xv * wv.y;
                    acc[r].z += xv * wv.z; acc[r].w += xv * wv.w;
                }
            }
        }
        float4 b = bs[l];
#pragma unroll
        for (int r = 0; r < 4; r++) {
            int row = row0 + r;
            if (row >= n) break;
            ((float4*)(out + (size_t)row * 128))[l] =
                make_float4(acc[r].x + b.x, acc[r].y + b.y,
                            acc[r].z + b.z, acc[r].w + b.w);
        }
    }
}

// ------------------------------- launch ----------------------------------
extern "C" void kernel_launch(void* const* d_in, const int* in_sizes, int n_in,
                              void* d_out, int out_size)
{
    const float* x    = (const float*)d_in[0];
    const int*   ei   = (const int*)d_in[1];
    const float* W1   = (const float*)d_in[2];
    const float* asr1 = (const float*)d_in[3];
    const float* ads1 = (const float*)d_in[4];
    const float* b1   = (const float*)d_in[5];
    const float* W2   = (const float*)d_in[6];
    const float* asr2 = (const float*)d_in[7];
    const float* ads2 = (const float*)d_in[8];
    const float* b2   = (const float*)d_in[9];
    float* out = (float*)d_out;

    int N  = in_sizes[0] / 128;
    int E  = in_sizes[1] / 2;
    int vec = ((E & 3) == 0) ? 1 : 0;
    int e4 = (E + 3) / 4;

    k_hist<<<(e4 + 255) / 256, 256>>>(ei, E, vec, W2, asr2, ads2);
    k_scan<<<1, 1024>>>(N);

    int ntb = ((N + 3) / 4 + 7) / 8;
    int sb  = (e4 + 255) / 256;
    int G   = 2 * (ntb > sb ? ntb : sb);
    k_gemm1_scatter<<<G, 256>>>(x, W1, asr1, ads1, N, ei, E, vec);

    k_agg1<<<1184, 256>>>(b1, N);
    k_agg2<<<(N + 7) / 8, 256>>>(N);
    k_gemmF<<<ntb, 256>>>(W2, b2, out, N);
}